// round 9
// baseline (speedup 1.0000x reference)
#include <cuda_runtime.h>
#include <cuda_bf16.h>
#include <cstdint>

#define N_SERIES 2048
#define N_TIME   4096
#define INPUT_SIZE 28
#define OUTPUT_SIZE 7
#define SEAS 7
#define EMB  9
#define S_LEN (N_TIME + SEAS)   /* 4103 */

#define OFF_YHAT 0
#define OFF_YWIN 401408
#define OFF_LEV  501760
#define OFF_SEAS (501760 + N_SERIES * N_TIME)

/* 39 relay chunks x 105-step body, WARM=455 (65 periods; rel_err 2.6e-5
   operating point HW-validated in R8). Chunks 0..4 start exact at t=1.
   Fine states every 35 steps -> 117 fine chunks for the store pass.
   Gauge mode removed exactly by the chain fixup. */
#define NCH1 39
#define BODY1 105
#define WARM 455
#define TS   35
#define NCH2 117

__device__ float g_flev  [NCH2][N_SERIES];
__device__ float g_fring [NCH2][SEAS][N_SERIES];
__device__ float g_endlev[NCH1][N_SERIES];
__device__ float g_gam   [NCH2][N_SERIES];

__device__ __forceinline__ float frcp(float x) {
    float r;
    asm("rcp.approx.f32 %0, %1;" : "=f"(r) : "f"(x));
    return r;
}

__device__ __forceinline__ void load_params(const int* idxs, const float* emb,
                                            int s, float& a, float& oma,
                                            float& b, float& omb, float* is)
{
    const float* ew = emb + (size_t)idxs[s] * EMB;
    a = 1.0f / (1.0f + __expf(-ew[0]));
    b = 1.0f / (1.0f + __expf(-ew[1]));
    oma = 1.0f - a;
    omb = 1.0f - b;
#pragma unroll
    for (int k = 0; k < SEAS; k++) is[k] = __expf(ew[2 + k]);
}

/* transpose-load one [32 series] x [35 steps] tile into time-major smem.
   STS bank = (t*33 + r) % 32 -> conflict-free; LDG lane-consecutive. */
__device__ __forceinline__ void load_tile(float (*ty)[33], const float* ygrp,
                                          int tstart, int lane)
{
#pragma unroll 8
    for (int r = 0; r < 32; r++) {
        const float* row = ygrp + (r << 12) + tstart;
        ty[lane][r] = __ldg(row + lane);
        if (lane < TS - 32) ty[lane + 32][r] = __ldg(row + lane + 32);
    }
}

/* Hand-pipelined period-batched scan.
   Phase 1: batch 7 LDS. Phase 2: independent FMULs. Phase 3: 7-FMA lev
   chain (4 cyc/step spine) with frcp(lev) dangling. Phase 4: deferred
   season updates — 7 independent (FMUL,FMA,MUFU,FMUL) groups.
   Exactly the reference math: ring[j] is read/written once per period.
   When STORE: lev overwrites the consumed y slot (ty doubles as L tile). */
template<bool STORE>
__device__ __forceinline__ void scan_tile(float (*ty)[33], float (*tsb)[33],
                                          int lane, float a, float oma,
                                          float b, float omb,
                                          float& lev, float* ring, float* aq)
{
#pragma unroll
    for (int g = 0; g < TS / SEAS; g++) {
        float yt[SEAS], ax[SEAS], bx[SEAS], ql[SEAS];
#pragma unroll
        for (int j = 0; j < SEAS; j++) yt[j] = ty[g * SEAS + j][lane];
#pragma unroll
        for (int j = 0; j < SEAS; j++) ax[j] = yt[j] * aq[j];
#pragma unroll
        for (int j = 0; j < SEAS; j++) bx[j] = b * yt[j];
#pragma unroll
        for (int j = 0; j < SEAS; j++) {
            lev = fmaf(oma, lev, ax[j]);
            if (STORE) ty[g * SEAS + j][lane] = lev;
            ql[j] = frcp(lev);
        }
#pragma unroll
        for (int j = 0; j < SEAS; j++) {
            float ns = fmaf(omb, ring[j], bx[j] * ql[j]);
            if (STORE) tsb[g * SEAS + j][lane] = ns;
            ring[j] = ns;
            aq[j]   = a * frcp(ns);
        }
    }
}

/* ---- Pass A: warmup + body per relay chunk, record fine states ---- */
__global__ void __launch_bounds__(32)
passA_kernel(const float* __restrict__ y, const int* __restrict__ idxs,
             const float* __restrict__ emb)
{
    __shared__ float ty[TS][33];
    const int c    = blockIdx.x / 64;
    const int sg   = blockIdx.x % 64;
    const int lane = threadIdx.x;
    const int s    = sg * 32 + lane;

    float a, oma, b, omb, is[SEAS];
    load_params(idxs, emb, s, a, oma, b, omb, is);

    const int tc = c * BODY1 + 1;
    int t0 = tc - WARM;
    if (t0 < 1) t0 = 1;
    const int wtiles = (tc - t0) / TS;
    const int ntiles = wtiles + 3;

    float lev = __fdividef(__ldg(y + (size_t)s * N_TIME + (t0 - 1)), is[0]);
    float ring[SEAS] = { is[1], is[2], is[3], is[4], is[5], is[6], is[0] };
    float aq[SEAS];
#pragma unroll
    for (int j = 0; j < SEAS; j++) aq[j] = a * frcp(ring[j]);

    const float* ygrp = y + (size_t)(sg * 32) * N_TIME;

#pragma unroll 1
    for (int tile = 0; tile < ntiles; tile++) {
        const int tstart = t0 + tile * TS;
        load_tile(ty, ygrp, tstart, lane);
        __syncwarp();

        if (tile >= wtiles) {
            const int m = 3 * c + (tile - wtiles);
            g_flev[m][s] = lev;
#pragma unroll
            for (int j = 0; j < SEAS; j++) g_fring[m][j][s] = ring[j];
        }

        scan_tile<false>(ty, 0, lane, a, oma, b, omb, lev, ring, aq);
        __syncwarp();
    }
    g_endlev[c][s] = lev;
}

/* ---- gauge chain: lambda_c = lambda_{c-1} * flev[3c]/endlev[c-1] ---- */
__global__ void fixup_kernel()
{
    int s = blockIdx.x * blockDim.x + threadIdx.x;
    if (s >= N_SERIES) return;
    float kap = 1.0f;
#pragma unroll
    for (int c = 0; c < NCH1; c++) {
        if (c >= 5)
            kap *= __fdividef(g_flev[3 * c][s], g_endlev[c - 1][s]);
        g_gam[3 * c][s]     = kap;
        g_gam[3 * c + 1][s] = kap;
        g_gam[3 * c + 2][s] = kap;
    }
}

/* ---- Pass C: 117 fine chunks x 35 steps, gauge-corrected, stores L,S ---- */
__global__ void __launch_bounds__(32)
passC_kernel(const float* __restrict__ y, const int* __restrict__ idxs,
             const float* __restrict__ emb,
             float* __restrict__ L, float* __restrict__ S)
{
    __shared__ float ty[TS][33];   /* y tile -> L tile (slot reuse) */
    __shared__ float ts[TS][33];
    const int m    = blockIdx.x / 64;
    const int sg   = blockIdx.x % 64;
    const int lane = threadIdx.x;
    const int s    = sg * 32 + lane;

    const int tstart = m * TS + 1;
    const float* ygrp = y + (size_t)(sg * 32) * N_TIME;

    load_tile(ty, ygrp, tstart, lane);

    float a, oma, b, omb, is[SEAS];
    load_params(idxs, emb, s, a, oma, b, omb, is);

    const float gam = g_gam[m][s];
    float lev = g_flev[m][s] * frcp(gam);
    float ring[SEAS], aq[SEAS];
#pragma unroll
    for (int j = 0; j < SEAS; j++) {
        ring[j] = g_fring[m][j][s] * gam;
        aq[j]   = a * frcp(ring[j]);
    }

    if (m == 0) {
        float* Sr = S + (size_t)s * S_LEN;
#pragma unroll
        for (int k = 0; k < SEAS; k++) Sr[k] = is[k];
        Sr[SEAS] = is[0];
        L[(size_t)s * N_TIME] = lev;
    }
    __syncwarp();

    scan_tile<true>(ty, ts, lane, a, oma, b, omb, lev, ring, aq);
    __syncwarp();

    /* coalesced flush: thread = time offset */
    {
        float* Lp = L + (size_t)(sg * 32) * N_TIME + tstart + lane;
        float* Sp = S + (size_t)(sg * 32) * S_LEN + tstart + SEAS + lane;
#pragma unroll 8
        for (int r = 0; r < 32; r++) {
            Lp[0] = ty[lane][r];
            Sp[0] = ts[lane][r];
            if (lane < TS - 32) {
                Lp[32] = ty[lane + 32][r];
                Sp[32] = ts[lane + 32][r];
            }
            Lp += N_TIME; Sp += S_LEN;
        }
    }
}

__global__ void windows_kernel(const float* __restrict__ y,
                               const float* __restrict__ L,
                               const float* __restrict__ S,
                               float* __restrict__ yhat,
                               float* __restrict__ ywin)
{
    const int NH = OUTPUT_SIZE * N_SERIES * INPUT_SIZE;   /* 401408 */
    const int NZ = OUTPUT_SIZE * N_SERIES * OUTPUT_SIZE;  /* 100352 */
    int i = blockIdx.x * blockDim.x + threadIdx.x;
    if (i < NH) {
        int ii   = i % INPUT_SIZE;
        int rest = i / INPUT_SIZE;
        int s    = rest % N_SERIES;
        int w    = rest / N_SERIES;
        int start = N_TIME - INPUT_SIZE - OUTPUT_SIZE + 1 + w;
        int t = start + ii;
        float lev = L[(size_t)s * N_TIME + (start + INPUT_SIZE - 1)];
        float se  = S[(size_t)s * S_LEN  + t];
        float yy  = y[(size_t)s * N_TIME + t];
        yhat[i] = logf(yy / (lev * se));
    } else if (i < NH + NZ) {
        ywin[i - NH] = 0.0f;
    }
}

extern "C" void kernel_launch(void* const* d_in, const int* in_sizes, int n_in,
                              void* d_out, int out_size) {
    const float* y    = (const float*)d_in[0];
    const int*   idxs = (const int*)  d_in[1];
    const float* emb  = (const float*)d_in[2];

    float* out  = (float*)d_out;
    float* yhat = out + OFF_YHAT;
    float* ywin = out + OFF_YWIN;
    float* L    = out + OFF_LEV;
    float* S    = out + OFF_SEAS;

    passA_kernel<<<NCH1 * 64, 32>>>(y, idxs, emb);
    fixup_kernel<<<(N_SERIES + 255) / 256, 256>>>();
    passC_kernel<<<NCH2 * 64, 32>>>(y, idxs, emb, L, S);

    const int tot = OUTPUT_SIZE * N_SERIES * (INPUT_SIZE + OUTPUT_SIZE); /* 501760 */
    windows_kernel<<<(tot + 255) / 256, 256>>>(y, L, S, yhat, ywin);
}

// round 10
// speedup vs baseline: 1.1151x; 1.1151x over previous
#include <cuda_runtime.h>
#include <cuda_bf16.h>
#include <cstdint>

#define N_SERIES 2048
#define N_TIME   4096
#define INPUT_SIZE 28
#define OUTPUT_SIZE 7
#define SEAS 7
#define EMB  9
#define S_LEN (N_TIME + SEAS)   /* 4103 */

#define OFF_YHAT 0
#define OFF_YWIN 401408
#define OFF_LEV  501760
#define OFF_SEAS (501760 + N_SERIES * N_TIME)

/* 39 relay chunks x 105-step body, WARM=385 (55 periods; predicted rel_err
   ~1.2e-4 from the HW-validated anchor 2.56e-5 @ WARM=455, contraction
   0.857/period). Chunks with t0 clamped to 1 are exact. Fine states every
   35 steps -> 117 fine chunks; gauge chain computed inside passC. */
#define NCH1 39
#define BODY1 105
#define WARM 385
#define TS   35
#define NCH2 117

__device__ float g_flev  [NCH2][N_SERIES];
__device__ float g_fring [NCH2][SEAS][N_SERIES];
__device__ float g_endlev[NCH1][N_SERIES];

__device__ __forceinline__ float frcp(float x) {
    float r;
    asm("rcp.approx.f32 %0, %1;" : "=f"(r) : "f"(x));
    return r;
}

__device__ __forceinline__ void load_params(const int* idxs, const float* emb,
                                            int s, float& a, float& oma,
                                            float& b, float& omb, float* is)
{
    const float* ew = emb + (size_t)idxs[s] * EMB;
    a = 1.0f / (1.0f + __expf(-ew[0]));
    b = 1.0f / (1.0f + __expf(-ew[1]));
    oma = 1.0f - a;
    omb = 1.0f - b;
#pragma unroll
    for (int k = 0; k < SEAS; k++) is[k] = __expf(ew[2 + k]);
}

/* transpose-load one [32 series] x [35 steps] tile into time-major smem.
   STS bank = (t*33 + r) % 32 -> conflict-free; LDG lane-consecutive. */
__device__ __forceinline__ void load_tile(float (*ty)[33], const float* ygrp,
                                          int tstart, int lane)
{
#pragma unroll 8
    for (int r = 0; r < 32; r++) {
        const float* row = ygrp + (r << 12) + tstart;
        ty[lane][r] = __ldg(row + lane);
        if (lane < TS - 32) ty[lane + 32][r] = __ldg(row + lane + 32);
    }
}

/* period-batched scan: 7 batched LDS; independent FMULs; 7-FMA lev chain
   with frcp(lev) dangling; deferred season updates (7 independent groups).
   When STORE: lev overwrites the consumed y slot (ty doubles as L tile). */
template<bool STORE>
__device__ __forceinline__ void scan_tile(float (*ty)[33], float (*tsb)[33],
                                          int lane, float a, float oma,
                                          float b, float omb,
                                          float& lev, float* ring, float* aq)
{
#pragma unroll
    for (int g = 0; g < TS / SEAS; g++) {
        float yt[SEAS], ax[SEAS], bx[SEAS], ql[SEAS];
#pragma unroll
        for (int j = 0; j < SEAS; j++) yt[j] = ty[g * SEAS + j][lane];
#pragma unroll
        for (int j = 0; j < SEAS; j++) ax[j] = yt[j] * aq[j];
#pragma unroll
        for (int j = 0; j < SEAS; j++) bx[j] = b * yt[j];
#pragma unroll
        for (int j = 0; j < SEAS; j++) {
            lev = fmaf(oma, lev, ax[j]);
            if (STORE) ty[g * SEAS + j][lane] = lev;
            ql[j] = frcp(lev);
        }
#pragma unroll
        for (int j = 0; j < SEAS; j++) {
            float ns = fmaf(omb, ring[j], bx[j] * ql[j]);
            if (STORE) tsb[g * SEAS + j][lane] = ns;
            ring[j] = ns;
            aq[j]   = a * frcp(ns);
        }
    }
}

/* dummy kernels: shift the ncu capture (launch index 3) onto passA */
__global__ void dummy_kernel() {}

/* ---- Pass A: warmup + body per relay chunk, record fine states ---- */
__global__ void __launch_bounds__(32)
passA_kernel(const float* __restrict__ y, const int* __restrict__ idxs,
             const float* __restrict__ emb)
{
    __shared__ float ty[TS][33];
    const int c    = blockIdx.x / 64;
    const int sg   = blockIdx.x % 64;
    const int lane = threadIdx.x;
    const int s    = sg * 32 + lane;

    float a, oma, b, omb, is[SEAS];
    load_params(idxs, emb, s, a, oma, b, omb, is);

    const int tc = c * BODY1 + 1;
    int t0 = tc - WARM;
    if (t0 < 1) t0 = 1;
    const int wtiles = (tc - t0) / TS;
    const int ntiles = wtiles + 3;

    float lev = __fdividef(__ldg(y + (size_t)s * N_TIME + (t0 - 1)), is[0]);
    float ring[SEAS] = { is[1], is[2], is[3], is[4], is[5], is[6], is[0] };
    float aq[SEAS];
#pragma unroll
    for (int j = 0; j < SEAS; j++) aq[j] = a * frcp(ring[j]);

    const float* ygrp = y + (size_t)(sg * 32) * N_TIME;

#pragma unroll 1
    for (int tile = 0; tile < ntiles; tile++) {
        const int tstart = t0 + tile * TS;
        load_tile(ty, ygrp, tstart, lane);
        __syncwarp();

        if (tile >= wtiles) {
            const int m = 3 * c + (tile - wtiles);
            g_flev[m][s] = lev;
#pragma unroll
            for (int j = 0; j < SEAS; j++) g_fring[m][j][s] = ring[j];
        }

        scan_tile<false>(ty, 0, lane, a, oma, b, omb, lev, ring, aq);
        __syncwarp();
    }
    g_endlev[c][s] = lev;
}

/* ---- Pass C: gauge chain inline, 117 fine chunks, stores L,S ---- */
__global__ void __launch_bounds__(32)
passC_kernel(const float* __restrict__ y, const int* __restrict__ idxs,
             const float* __restrict__ emb,
             float* __restrict__ L, float* __restrict__ S)
{
    __shared__ float ty[TS][33];   /* y tile -> L tile (slot reuse) */
    __shared__ float ts[TS][33];
    const int m    = blockIdx.x / 64;
    const int sg   = blockIdx.x % 64;
    const int lane = threadIdx.x;
    const int s    = sg * 32 + lane;

    const int tstart = m * TS + 1;
    const float* ygrp = y + (size_t)(sg * 32) * N_TIME;

    load_tile(ty, ygrp, tstart, lane);

    float a, oma, b, omb, is[SEAS];
    load_params(idxs, emb, s, a, oma, b, omb, is);

    /* gauge of this fine chunk: product over full-warmup links <= c=m/3.
       Links start at chunk 4 (first with t0 unclamped: 4*105 >= 385). */
    const int c = m / 3;
    float gam = 1.0f;
    for (int k = 4; k <= c; k++)
        gam *= __fdividef(g_flev[3 * k][s], g_endlev[k - 1][s]);

    float lev = g_flev[m][s] * frcp(gam);
    float ring[SEAS], aq[SEAS];
#pragma unroll
    for (int j = 0; j < SEAS; j++) {
        ring[j] = g_fring[m][j][s] * gam;
        aq[j]   = a * frcp(ring[j]);
    }

    if (m == 0) {
        float* Sr = S + (size_t)s * S_LEN;
#pragma unroll
        for (int k = 0; k < SEAS; k++) Sr[k] = is[k];
        Sr[SEAS] = is[0];
        L[(size_t)s * N_TIME] = lev;
    }
    __syncwarp();

    scan_tile<true>(ty, ts, lane, a, oma, b, omb, lev, ring, aq);
    __syncwarp();

    /* coalesced flush: thread = time offset */
    {
        float* Lp = L + (size_t)(sg * 32) * N_TIME + tstart + lane;
        float* Sp = S + (size_t)(sg * 32) * S_LEN + tstart + SEAS + lane;
#pragma unroll 8
        for (int r = 0; r < 32; r++) {
            Lp[0] = ty[lane][r];
            Sp[0] = ts[lane][r];
            if (lane < TS - 32) {
                Lp[32] = ty[lane + 32][r];
                Sp[32] = ts[lane + 32][r];
            }
            Lp += N_TIME; Sp += S_LEN;
        }
    }
}

__global__ void windows_kernel(const float* __restrict__ y,
                               const float* __restrict__ L,
                               const float* __restrict__ S,
                               float* __restrict__ yhat,
                               float* __restrict__ ywin)
{
    const int NH = OUTPUT_SIZE * N_SERIES * INPUT_SIZE;   /* 401408 */
    const int NZ = OUTPUT_SIZE * N_SERIES * OUTPUT_SIZE;  /* 100352 */
    int i = blockIdx.x * blockDim.x + threadIdx.x;
    if (i < NH) {
        int ii   = i % INPUT_SIZE;
        int rest = i / INPUT_SIZE;
        int s    = rest % N_SERIES;
        int w    = rest / N_SERIES;
        int start = N_TIME - INPUT_SIZE - OUTPUT_SIZE + 1 + w;
        int t = start + ii;
        float lev = L[(size_t)s * N_TIME + (start + INPUT_SIZE - 1)];
        float se  = S[(size_t)s * S_LEN  + t];
        float yy  = y[(size_t)s * N_TIME + t];
        yhat[i] = logf(yy / (lev * se));
    } else if (i < NH + NZ) {
        ywin[i - NH] = 0.0f;
    }
}

extern "C" void kernel_launch(void* const* d_in, const int* in_sizes, int n_in,
                              void* d_out, int out_size) {
    const float* y    = (const float*)d_in[0];
    const int*   idxs = (const int*)  d_in[1];
    const float* emb  = (const float*)d_in[2];

    float* out  = (float*)d_out;
    float* yhat = out + OFF_YHAT;
    float* ywin = out + OFF_YWIN;
    float* L    = out + OFF_LEV;
    float* S    = out + OFF_SEAS;

    /* launches 0-2: dummies so the ncu capture (launch #3) profiles passA */
    dummy_kernel<<<1, 32>>>();
    dummy_kernel<<<1, 32>>>();
    dummy_kernel<<<1, 32>>>();

    passA_kernel<<<NCH1 * 64, 32>>>(y, idxs, emb);
    passC_kernel<<<NCH2 * 64, 32>>>(y, idxs, emb, L, S);

    const int tot = OUTPUT_SIZE * N_SERIES * (INPUT_SIZE + OUTPUT_SIZE); /* 501760 */
    windows_kernel<<<(tot + 255) / 256, 256>>>(y, L, S, yhat, ywin);
}

// round 11
// speedup vs baseline: 1.2567x; 1.1270x over previous
#include <cuda_runtime.h>
#include <cuda_bf16.h>
#include <cstdint>

#define N_SERIES 2048
#define N_TIME   4096
#define INPUT_SIZE 28
#define OUTPUT_SIZE 7
#define SEAS 7
#define EMB  9
#define S_LEN (N_TIME + SEAS)   /* 4103 */

#define OFF_YHAT 0
#define OFF_YWIN 401408
#define OFF_LEV  501760
#define OFF_SEAS (501760 + N_SERIES * N_TIME)

/* 39 relay chunks x 105-step body, WARM=350 (50 periods; predicted rel_err
   ~2.7e-4 from HW-validated anchors 2.56e-5@65per, 1.26e-4@55per, contraction
   0.857/period). Chunks with t0 clamped to 1 are exact. Fine states every
   35 steps -> 117 fine chunks; gauge chain computed inside passC. */
#define NCH1 39
#define BODY1 105
#define WARM 350
#define TS   35
#define NCH2 117

__device__ float g_flev  [NCH2][N_SERIES];
__device__ float g_fring [NCH2][SEAS][N_SERIES];
__device__ float g_endlev[NCH1][N_SERIES];

__device__ __forceinline__ float frcp(float x) {
    float r;
    asm("rcp.approx.f32 %0, %1;" : "=f"(r) : "f"(x));
    return r;
}
__device__ __forceinline__ uint32_t s2u(const void* p) {
    uint32_t a;
    asm("{ .reg .u64 t; cvta.to.shared.u64 t, %1; cvt.u32.u64 %0, t; }"
        : "=r"(a) : "l"(p));
    return a;
}
__device__ __forceinline__ void cp4(uint32_t d, const float* g) {
    asm volatile("cp.async.ca.shared.global [%0], [%1], 4;" :: "r"(d), "l"(g));
}
#define CP_COMMIT() asm volatile("cp.async.commit_group;" ::: "memory")
#define CP_WAIT0()  asm volatile("cp.async.wait_group 0;" ::: "memory")
#define CP_WAIT1()  asm volatile("cp.async.wait_group 1;" ::: "memory")

__device__ __forceinline__ void load_params(const int* idxs, const float* emb,
                                            int s, float& a, float& oma,
                                            float& b, float& omb, float* is)
{
    const float* ew = emb + (size_t)idxs[s] * EMB;
    a = 1.0f / (1.0f + __expf(-ew[0]));
    b = 1.0f / (1.0f + __expf(-ew[1]));
    oma = 1.0f - a;
    omb = 1.0f - b;
#pragma unroll
    for (int k = 0; k < SEAS; k++) is[k] = __expf(ew[2 + k]);
}

/* async transpose-load of [32 series] x [35 steps] into time-major smem.
   Main 32x32: iteration r copies y[row r][tstart+lane] -> smem[lane][r]
   (gmem coalesced, 1 line/req). Tail 3 steps: lanes = rows (uncoalesced but
   only 96 x 4B, async). smem bank (t*33+r) -> conflict-free for the scan. */
__device__ __forceinline__ void tile_cp(uint32_t sbase, const float* ygrp,
                                        int tstart, int lane)
{
    const float* src = ygrp + tstart + lane;
    uint32_t dst = sbase + (uint32_t)(lane * 33) * 4;
#pragma unroll
    for (int r = 0; r < 32; r++) {
        cp4(dst, src);
        src += N_TIME;
        dst += 4;
    }
#pragma unroll
    for (int p = 0; p < 3; p++)
        cp4(sbase + (uint32_t)((32 + p) * 33 + lane) * 4,
            ygrp + ((size_t)lane << 12) + tstart + 32 + p);
}

/* period-batched scan: 7 batched LDS; independent FMULs; 7-FMA lev chain
   with frcp(lev) dangling; deferred season updates (7 independent groups).
   When STORE: lev overwrites the consumed y slot (ty doubles as L tile). */
template<bool STORE>
__device__ __forceinline__ void scan_tile(float (*ty)[33], float (*tsb)[33],
                                          int lane, float a, float oma,
                                          float b, float omb,
                                          float& lev, float* ring, float* aq)
{
#pragma unroll
    for (int g = 0; g < TS / SEAS; g++) {
        float yt[SEAS], ax[SEAS], bx[SEAS], ql[SEAS];
#pragma unroll
        for (int j = 0; j < SEAS; j++) yt[j] = ty[g * SEAS + j][lane];
#pragma unroll
        for (int j = 0; j < SEAS; j++) ax[j] = yt[j] * aq[j];
#pragma unroll
        for (int j = 0; j < SEAS; j++) bx[j] = b * yt[j];
#pragma unroll
        for (int j = 0; j < SEAS; j++) {
            lev = fmaf(oma, lev, ax[j]);
            if (STORE) ty[g * SEAS + j][lane] = lev;
            ql[j] = frcp(lev);
        }
#pragma unroll
        for (int j = 0; j < SEAS; j++) {
            float ns = fmaf(omb, ring[j], bx[j] * ql[j]);
            if (STORE) tsb[g * SEAS + j][lane] = ns;
            ring[j] = ns;
            aq[j]   = a * frcp(ns);
        }
    }
}

/* dummy kernels: keep the ncu capture (launch index 3) on passA */
__global__ void dummy_kernel() {}

/* ---- Pass A: warmup + body per relay chunk, record fine states ---- */
__global__ void __launch_bounds__(32)
passA_kernel(const float* __restrict__ y, const int* __restrict__ idxs,
             const float* __restrict__ emb)
{
    __shared__ float ty[2][TS][33];
    const int c    = blockIdx.x / 64;
    const int sg   = blockIdx.x % 64;
    const int lane = threadIdx.x;
    const int s    = sg * 32 + lane;

    const float* ygrp = y + (size_t)(sg * 32) * N_TIME;
    const uint32_t tyb0 = s2u(&ty[0][0][0]);
    const uint32_t tyb1 = s2u(&ty[1][0][0]);

    const int tc = c * BODY1 + 1;
    int t0 = tc - WARM;
    if (t0 < 1) t0 = 1;
    const int wtiles = (tc - t0) / TS;
    const int ntiles = wtiles + 3;

    /* prefetch tile 0, then do parameter math under the load */
    tile_cp(tyb0, ygrp, t0, lane);
    CP_COMMIT();

    float a, oma, b, omb, is[SEAS];
    load_params(idxs, emb, s, a, oma, b, omb, is);

    float lev = __fdividef(__ldg(y + (size_t)s * N_TIME + (t0 - 1)), is[0]);
    float ring[SEAS] = { is[1], is[2], is[3], is[4], is[5], is[6], is[0] };
    float aq[SEAS];
#pragma unroll
    for (int j = 0; j < SEAS; j++) aq[j] = a * frcp(ring[j]);

#pragma unroll 1
    for (int tile = 0; tile < ntiles; tile++) {
        const int buf = tile & 1;
        if (tile + 1 < ntiles) {
            tile_cp(buf ? tyb0 : tyb1, ygrp, t0 + (tile + 1) * TS, lane);
            CP_COMMIT();
            CP_WAIT1();
        } else {
            CP_WAIT0();
        }
        __syncwarp();

        if (tile >= wtiles) {
            const int m = 3 * c + (tile - wtiles);
            g_flev[m][s] = lev;
#pragma unroll
            for (int j = 0; j < SEAS; j++) g_fring[m][j][s] = ring[j];
        }

        scan_tile<false>(ty[buf], 0, lane, a, oma, b, omb, lev, ring, aq);
        __syncwarp();
    }
    g_endlev[c][s] = lev;
}

/* ---- Pass C: gauge chain inline, 117 fine chunks, stores L,S ---- */
__global__ void __launch_bounds__(32)
passC_kernel(const float* __restrict__ y, const int* __restrict__ idxs,
             const float* __restrict__ emb,
             float* __restrict__ L, float* __restrict__ S)
{
    __shared__ float ty[TS][33];   /* y tile -> L tile (slot reuse) */
    __shared__ float ts[TS][33];
    const int m    = blockIdx.x / 64;
    const int sg   = blockIdx.x % 64;
    const int lane = threadIdx.x;
    const int s    = sg * 32 + lane;

    const int tstart = m * TS + 1;
    const float* ygrp = y + (size_t)(sg * 32) * N_TIME;

    /* async tile load overlaps the gauge-chain prologue below */
    tile_cp(s2u(&ty[0][0]), ygrp, tstart, lane);
    CP_COMMIT();

    float a, oma, b, omb, is[SEAS];
    load_params(idxs, emb, s, a, oma, b, omb, is);

    /* gauge of this fine chunk: product over full-warmup links <= c=m/3.
       Links start at chunk 4 (first with t0 unclamped: 4*105 >= 350). */
    const int c = m / 3;
    float gam = 1.0f;
    for (int k = 4; k <= c; k++)
        gam *= __fdividef(g_flev[3 * k][s], g_endlev[k - 1][s]);

    float lev = g_flev[m][s] * frcp(gam);
    float ring[SEAS], aq[SEAS];
#pragma unroll
    for (int j = 0; j < SEAS; j++) {
        ring[j] = g_fring[m][j][s] * gam;
        aq[j]   = a * frcp(ring[j]);
    }

    if (m == 0) {
        float* Sr = S + (size_t)s * S_LEN;
#pragma unroll
        for (int k = 0; k < SEAS; k++) Sr[k] = is[k];
        Sr[SEAS] = is[0];
        L[(size_t)s * N_TIME] = lev;
    }

    CP_WAIT0();
    __syncwarp();

    scan_tile<true>(ty, ts, lane, a, oma, b, omb, lev, ring, aq);
    __syncwarp();

    /* coalesced flush: thread = time offset; LDS (lane+r) mod 32 distinct */
    {
        float* Lp = L + (size_t)(sg * 32) * N_TIME + tstart + lane;
        float* Sp = S + (size_t)(sg * 32) * S_LEN + tstart + SEAS + lane;
#pragma unroll 8
        for (int r = 0; r < 32; r++) {
            Lp[0] = ty[lane][r];
            Sp[0] = ts[lane][r];
            if (lane < TS - 32) {
                Lp[32] = ty[lane + 32][r];
                Sp[32] = ts[lane + 32][r];
            }
            Lp += N_TIME; Sp += S_LEN;
        }
    }
}

__global__ void windows_kernel(const float* __restrict__ y,
                               const float* __restrict__ L,
                               const float* __restrict__ S,
                               float* __restrict__ yhat,
                               float* __restrict__ ywin)
{
    const int NH = OUTPUT_SIZE * N_SERIES * INPUT_SIZE;   /* 401408 */
    const int NZ = OUTPUT_SIZE * N_SERIES * OUTPUT_SIZE;  /* 100352 */
    int i = blockIdx.x * blockDim.x + threadIdx.x;
    if (i < NH) {
        int ii   = i % INPUT_SIZE;
        int rest = i / INPUT_SIZE;
        int s    = rest % N_SERIES;
        int w    = rest / N_SERIES;
        int start = N_TIME - INPUT_SIZE - OUTPUT_SIZE + 1 + w;
        int t = start + ii;
        float lev = L[(size_t)s * N_TIME + (start + INPUT_SIZE - 1)];
        float se  = S[(size_t)s * S_LEN  + t];
        float yy  = y[(size_t)s * N_TIME + t];
        yhat[i] = logf(yy / (lev * se));
    } else if (i < NH + NZ) {
        ywin[i - NH] = 0.0f;
    }
}

extern "C" void kernel_launch(void* const* d_in, const int* in_sizes, int n_in,
                              void* d_out, int out_size) {
    const float* y    = (const float*)d_in[0];
    const int*   idxs = (const int*)  d_in[1];
    const float* emb  = (const float*)d_in[2];

    float* out  = (float*)d_out;
    float* yhat = out + OFF_YHAT;
    float* ywin = out + OFF_YWIN;
    float* L    = out + OFF_LEV;
    float* S    = out + OFF_SEAS;

    /* launches 0-2: dummies so the ncu capture (launch #3) profiles passA */
    dummy_kernel<<<1, 32>>>();
    dummy_kernel<<<1, 32>>>();
    dummy_kernel<<<1, 32>>>();

    passA_kernel<<<NCH1 * 64, 32>>>(y, idxs, emb);
    passC_kernel<<<NCH2 * 64, 32>>>(y, idxs, emb, L, S);

    const int tot = OUTPUT_SIZE * N_SERIES * (INPUT_SIZE + OUTPUT_SIZE); /* 501760 */
    windows_kernel<<<(tot + 255) / 256, 256>>>(y, L, S, yhat, ywin);
}

// round 13
// speedup vs baseline: 1.2777x; 1.0167x over previous
#include <cuda_runtime.h>
#include <cuda_bf16.h>
#include <cstdint>

#define N_SERIES 2048
#define N_TIME   4096
#define INPUT_SIZE 28
#define OUTPUT_SIZE 7
#define SEAS 7
#define EMB  9
#define S_LEN (N_TIME + SEAS)   /* 4103 */

#define OFF_YHAT 0
#define OFF_YWIN 401408
#define OFF_LEV  501760
#define OFF_SEAS (501760 + N_SERIES * N_TIME)

/* 39 relay chunks x 105-step body, WARM=350 (50 periods; rel_err 2.7e-4
   HW-validated in R11). Chunks with t0 clamped to 1 are exact. Fine states
   every 35 steps -> 117 fine chunks; gauge chain computed inside passC. */
#define NCH1 39
#define BODY1 105
#define WARM 350
#define TS   35
#define NCH2 117

__device__ float g_flev  [NCH2][N_SERIES];
__device__ float g_fring [NCH2][SEAS][N_SERIES];
__device__ float g_endlev[NCH1][N_SERIES];

__device__ __forceinline__ float frcp(float x) {
    float r;
    asm("rcp.approx.f32 %0, %1;" : "=f"(r) : "f"(x));
    return r;
}
__device__ __forceinline__ uint32_t s2u(const void* p) {
    uint32_t a;
    asm("{ .reg .u64 t; cvta.to.shared.u64 t, %1; cvt.u32.u64 %0, t; }"
        : "=r"(a) : "l"(p));
    return a;
}
#define CP_COMMIT() asm volatile("cp.async.commit_group;" ::: "memory")
#define CP_WAIT0()  asm volatile("cp.async.wait_group 0;" ::: "memory")
#define CP_WAIT1()  asm volatile("cp.async.wait_group 1;" ::: "memory")

/* main transpose copy: iteration R copies y[row R][tstart+lane] ->
   smem[t=lane][series=R]. All offsets compile-time immediates:
   dst = dmain + R*4 bytes  (series is the INNER dim of float[35][33]),
   src = gmain + R*16384 bytes (row stride N_TIME*4). Zero per-op ALU.
   (dmain = smem base + lane*132 already folds in the t=lane row.) */
template<int R>
struct CpMain {
    static __device__ __forceinline__ void run(uint32_t d, const float* g) {
        asm volatile("cp.async.ca.shared.global [%0+%2], [%1+%3], 4;"
                     :: "r"(d), "l"(g), "n"(R * 4), "n"(R * 16384));
        CpMain<R + 1>::run(d, g);
    }
};
template<> struct CpMain<32> {
    static __device__ __forceinline__ void run(uint32_t, const float*) {}
};

/* tail: steps 32..34 for row=lane (column reads, 96 x 4B, async).
   dst = dtail + p*132 ([32+p][lane]), src = gtail + p*4. */
__device__ __forceinline__ void tile_cp(uint32_t dmain, uint32_t dtail,
                                        const float* gmain, const float* gtail)
{
    CpMain<0>::run(dmain, gmain);
    asm volatile("cp.async.ca.shared.global [%0+0], [%1+0], 4;"
                 :: "r"(dtail), "l"(gtail));
    asm volatile("cp.async.ca.shared.global [%0+132], [%1+4], 4;"
                 :: "r"(dtail), "l"(gtail));
    asm volatile("cp.async.ca.shared.global [%0+264], [%1+8], 4;"
                 :: "r"(dtail), "l"(gtail));
}

__device__ __forceinline__ void load_params(const int* idxs, const float* emb,
                                            int s, float& a, float& oma,
                                            float& b, float& omb, float* is)
{
    const float* ew = emb + (size_t)idxs[s] * EMB;
    a = 1.0f / (1.0f + __expf(-ew[0]));
    b = 1.0f / (1.0f + __expf(-ew[1]));
    oma = 1.0f - a;
    omb = 1.0f - b;
#pragma unroll
    for (int k = 0; k < SEAS; k++) is[k] = __expf(ew[2 + k]);
}

/* period-batched scan: 7 batched LDS; independent FMULs; 7-FMA lev chain
   with frcp(lev) dangling; deferred season updates (7 independent groups).
   When STORE: lev overwrites the consumed y slot (ty doubles as L tile). */
template<bool STORE>
__device__ __forceinline__ void scan_tile(float (*ty)[33], float (*tsb)[33],
                                          int lane, float a, float oma,
                                          float b, float omb,
                                          float& lev, float* ring, float* aq)
{
#pragma unroll
    for (int g = 0; g < TS / SEAS; g++) {
        float yt[SEAS], ax[SEAS], bx[SEAS], ql[SEAS];
#pragma unroll
        for (int j = 0; j < SEAS; j++) yt[j] = ty[g * SEAS + j][lane];
#pragma unroll
        for (int j = 0; j < SEAS; j++) ax[j] = yt[j] * aq[j];
#pragma unroll
        for (int j = 0; j < SEAS; j++) bx[j] = b * yt[j];
#pragma unroll
        for (int j = 0; j < SEAS; j++) {
            lev = fmaf(oma, lev, ax[j]);
            if (STORE) ty[g * SEAS + j][lane] = lev;
            ql[j] = frcp(lev);
        }
#pragma unroll
        for (int j = 0; j < SEAS; j++) {
            float ns = fmaf(omb, ring[j], bx[j] * ql[j]);
            if (STORE) tsb[g * SEAS + j][lane] = ns;
            ring[j] = ns;
            aq[j]   = a * frcp(ns);
        }
    }
}

/* dummy kernels: keep the ncu capture (launch index 3) on passA */
__global__ void dummy_kernel() {}

/* ---- Pass A: warmup + body per relay chunk, record fine states ---- */
__global__ void __launch_bounds__(32)
passA_kernel(const float* __restrict__ y, const int* __restrict__ idxs,
             const float* __restrict__ emb)
{
    __shared__ float ty[2][TS][33];
    const int c    = blockIdx.x / 64;
    const int sg   = blockIdx.x % 64;
    const int lane = threadIdx.x;
    const int s    = sg * 32 + lane;

    const float* ygrp = y + (size_t)(sg * 32) * N_TIME;
    /* per-thread copy bases (computed once) */
    const float* ymain = ygrp + lane;                      /* + tstart */
    const float* ytail = ygrp + ((size_t)lane << 12) + 32; /* + tstart */
    const uint32_t dm0 = s2u(&ty[0][0][0]) + (uint32_t)lane * 132;
    const uint32_t dm1 = s2u(&ty[1][0][0]) + (uint32_t)lane * 132;
    const uint32_t dt0 = s2u(&ty[0][32][0]) + (uint32_t)lane * 4;
    const uint32_t dt1 = s2u(&ty[1][32][0]) + (uint32_t)lane * 4;

    const int tc = c * BODY1 + 1;
    int t0 = tc - WARM;
    if (t0 < 1) t0 = 1;
    const int wtiles = (tc - t0) / TS;
    const int ntiles = wtiles + 3;

    /* prefetch tile 0, then do parameter math under the load */
    tile_cp(dm0, dt0, ymain + t0, ytail + t0);
    CP_COMMIT();

    float a, oma, b, omb, is[SEAS];
    load_params(idxs, emb, s, a, oma, b, omb, is);

    float lev = __fdividef(__ldg(y + (size_t)s * N_TIME + (t0 - 1)), is[0]);
    float ring[SEAS] = { is[1], is[2], is[3], is[4], is[5], is[6], is[0] };
    float aq[SEAS];
#pragma unroll
    for (int j = 0; j < SEAS; j++) aq[j] = a * frcp(ring[j]);

#pragma unroll 1
    for (int tile = 0; tile < ntiles; tile++) {
        const int buf = tile & 1;
        if (tile + 1 < ntiles) {
            const int tn = t0 + (tile + 1) * TS;
            tile_cp(buf ? dm0 : dm1, buf ? dt0 : dt1, ymain + tn, ytail + tn);
            CP_COMMIT();
            CP_WAIT1();
        } else {
            CP_WAIT0();
        }
        __syncwarp();

        if (tile >= wtiles) {
            const int m = 3 * c + (tile - wtiles);
            g_flev[m][s] = lev;
#pragma unroll
            for (int j = 0; j < SEAS; j++) g_fring[m][j][s] = ring[j];
        }

        scan_tile<false>(ty[buf], 0, lane, a, oma, b, omb, lev, ring, aq);
        __syncwarp();
    }
    g_endlev[c][s] = lev;
}

/* ---- Pass C: gauge chain inline, 117 fine chunks, stores L,S ---- */
__global__ void __launch_bounds__(32)
passC_kernel(const float* __restrict__ y, const int* __restrict__ idxs,
             const float* __restrict__ emb,
             float* __restrict__ L, float* __restrict__ S)
{
    __shared__ float ty[TS][33];   /* y tile -> L tile (slot reuse) */
    __shared__ float ts[TS][33];
    const int m    = blockIdx.x / 64;
    const int sg   = blockIdx.x % 64;
    const int lane = threadIdx.x;
    const int s    = sg * 32 + lane;

    const int tstart = m * TS + 1;
    const float* ygrp = y + (size_t)(sg * 32) * N_TIME;

    /* async tile load overlaps the gauge-chain prologue below */
    tile_cp(s2u(&ty[0][0]) + (uint32_t)lane * 132,
            s2u(&ty[32][0]) + (uint32_t)lane * 4,
            ygrp + lane + tstart,
            ygrp + ((size_t)lane << 12) + 32 + tstart);
    CP_COMMIT();

    float a, oma, b, omb, is[SEAS];
    load_params(idxs, emb, s, a, oma, b, omb, is);

    /* gauge of this fine chunk: product over full-warmup links <= c=m/3.
       Links start at chunk 4 (first with t0 unclamped: 4*105 >= 350). */
    const int c = m / 3;
    float gam = 1.0f;
    for (int k = 4; k <= c; k++)
        gam *= __fdividef(g_flev[3 * k][s], g_endlev[k - 1][s]);

    float lev = g_flev[m][s] * frcp(gam);
    float ring[SEAS], aq[SEAS];
#pragma unroll
    for (int j = 0; j < SEAS; j++) {
        ring[j] = g_fring[m][j][s] * gam;
        aq[j]   = a * frcp(ring[j]);
    }

    if (m == 0) {
        float* Sr = S + (size_t)s * S_LEN;
#pragma unroll
        for (int k = 0; k < SEAS; k++) Sr[k] = is[k];
        Sr[SEAS] = is[0];
        L[(size_t)s * N_TIME] = lev;
    }

    CP_WAIT0();
    __syncwarp();

    scan_tile<true>(ty, ts, lane, a, oma, b, omb, lev, ring, aq);
    __syncwarp();

    /* coalesced flush, immediate-offset stores (no pointer chains) */
    {
        float* Lb = L + (size_t)(sg * 32) * N_TIME + tstart + lane;
        float* Sb = S + (size_t)(sg * 32) * S_LEN + tstart + SEAS + lane;
#pragma unroll
        for (int r = 0; r < 32; r++) {
            Lb[(size_t)r * N_TIME] = ty[lane][r];
            Sb[(size_t)r * S_LEN]  = ts[lane][r];
            if (lane < TS - 32) {
                Lb[(size_t)r * N_TIME + 32] = ty[lane + 32][r];
                Sb[(size_t)r * S_LEN  + 32] = ts[lane + 32][r];
            }
        }
    }
}

__global__ void windows_kernel(const float* __restrict__ y,
                               const float* __restrict__ L,
                               const float* __restrict__ S,
                               float* __restrict__ yhat,
                               float* __restrict__ ywin)
{
    const int NH = OUTPUT_SIZE * N_SERIES * INPUT_SIZE;   /* 401408 */
    const int NZ = OUTPUT_SIZE * N_SERIES * OUTPUT_SIZE;  /* 100352 */
    int i = blockIdx.x * blockDim.x + threadIdx.x;
    if (i < NH) {
        int ii   = i % INPUT_SIZE;
        int rest = i / INPUT_SIZE;
        int s    = rest % N_SERIES;
        int w    = rest / N_SERIES;
        int start = N_TIME - INPUT_SIZE - OUTPUT_SIZE + 1 + w;
        int t = start + ii;
        float lev = L[(size_t)s * N_TIME + (start + INPUT_SIZE - 1)];
        float se  = S[(size_t)s * S_LEN  + t];
        float yy  = y[(size_t)s * N_TIME + t];
        yhat[i] = logf(yy / (lev * se));
    } else if (i < NH + NZ) {
        ywin[i - NH] = 0.0f;
    }
}

extern "C" void kernel_launch(void* const* d_in, const int* in_sizes, int n_in,
                              void* d_out, int out_size) {
    const float* y    = (const float*)d_in[0];
    const int*   idxs = (const int*)  d_in[1];
    const float* emb  = (const float*)d_in[2];

    float* out  = (float*)d_out;
    float* yhat = out + OFF_YHAT;
    float* ywin = out + OFF_YWIN;
    float* L    = out + OFF_LEV;
    float* S    = out + OFF_SEAS;

    /* launches 0-2: dummies so the ncu capture (launch #3) profiles passA */
    dummy_kernel<<<1, 32>>>();
    dummy_kernel<<<1, 32>>>();
    dummy_kernel<<<1, 32>>>();

    passA_kernel<<<NCH1 * 64, 32>>>(y, idxs, emb);
    passC_kernel<<<NCH2 * 64, 32>>>(y, idxs, emb, L, S);

    const int tot = OUTPUT_SIZE * N_SERIES * (INPUT_SIZE + OUTPUT_SIZE); /* 501760 */
    windows_kernel<<<(tot + 255) / 256, 256>>>(y, L, S, yhat, ywin);
}

// round 14
// speedup vs baseline: 1.3213x; 1.0341x over previous
#include <cuda_runtime.h>
#include <cuda_bf16.h>
#include <cstdint>

#define N_SERIES 2048
#define N_TIME   4096
#define INPUT_SIZE 28
#define OUTPUT_SIZE 7
#define SEAS 7
#define EMB  9
#define S_LEN (N_TIME + SEAS)   /* 4103 */

#define OFF_YHAT 0
#define OFF_YWIN 401408
#define OFF_LEV  501760
#define OFF_SEAS (501760 + N_SERIES * N_TIME)

/* Time grid: stub steps t=1..7 (scalar), then 146 fine chunks of 28 steps
   starting at t = 8+28m (16B-aligned, phase-aligned: (t-1) % 7 == 0).
   Relay: 49 chunks, BODY=84 (3 fines), WARM=364 (52 periods -> per-link
   error ~2e-4 by the HW-measured 0.857/period contraction law).
   Chunks 0..4 exact from t=1 (stub + tiles). Gauge chain from chunk 5,
   computed inline in passC. */
#define NCH1 49
#define BODY 84
#define WARM 364
#define TS   28
#define NCH2 146

__device__ float g_flev  [NCH2][N_SERIES];
__device__ float g_fring [NCH2][SEAS][N_SERIES];
__device__ float g_endlev[NCH1][N_SERIES];

__device__ __forceinline__ float frcp(float x) {
    float r;
    asm("rcp.approx.f32 %0, %1;" : "=f"(r) : "f"(x));
    return r;
}
__device__ __forceinline__ uint32_t s2u(const void* p) {
    uint32_t a;
    asm("{ .reg .u64 t; cvta.to.shared.u64 t, %1; cvt.u32.u64 %0, t; }"
        : "=r"(a) : "l"(p));
    return a;
}
__device__ __forceinline__ void cp16(uint32_t d, const float* g) {
    asm volatile("cp.async.ca.shared.global [%0], [%1], 16;" :: "r"(d), "l"(g));
}
#define CP_COMMIT() asm volatile("cp.async.commit_group;" ::: "memory")
#define CP_WAIT0()  asm volatile("cp.async.wait_group 0;" ::: "memory")
#define CP_WAIT1()  asm volatile("cp.async.wait_group 1;" ::: "memory")

/* coalesced 16B-chunk copy of a [32 series] x [28 floats] tile into
   series-major smem rows (112B = 7 x 16B per row). 224 chunks, 7/lane;
   consecutive lanes take consecutive chunks -> gmem runs coalesced.
   Requires tstart % 4 == 0 (guaranteed by the 8+28m grid). */
__device__ __forceinline__ void tile_cp(uint32_t sbase, const float* ygrp,
                                        int tstart, int lane)
{
#pragma unroll
    for (int p = 0; p < 7; p++) {
        unsigned item = (unsigned)(p * 32 + lane);
        unsigned r = item / 7u;
        unsigned k = item - 7u * r;
        cp16(sbase + r * 112u + k * 16u,
             ygrp + ((size_t)r << 12) + tstart + 4u * k);
    }
}

__device__ __forceinline__ void load_params(const int* idxs, const float* emb,
                                            int s, float& a, float& oma,
                                            float& b, float& omb, float* is)
{
    const float* ew = emb + (size_t)idxs[s] * EMB;
    a = 1.0f / (1.0f + __expf(-ew[0]));
    b = 1.0f / (1.0f + __expf(-ew[1]));
    oma = 1.0f - a;
    omb = 1.0f - b;
#pragma unroll
    for (int k = 0; k < SEAS; k++) is[k] = __expf(ew[2 + k]);
}

/* one 7-step period: independent FMULs; 7-FMA lev chain with frcp dangling;
   deferred season updates. Outputs (when STORE) go to time-major tiles. */
template<bool STORE>
__device__ __forceinline__ void step7(const float* yt,
                                      float (*tl)[33], float (*ts)[33],
                                      int toff, int lane,
                                      float a, float oma, float b, float omb,
                                      float& lev, float* ring, float* aq)
{
    float ax[SEAS], bx[SEAS], ql[SEAS];
#pragma unroll
    for (int j = 0; j < SEAS; j++) { ax[j] = yt[j] * aq[j]; bx[j] = b * yt[j]; }
#pragma unroll
    for (int j = 0; j < SEAS; j++) {
        lev = fmaf(oma, lev, ax[j]);
        if (STORE) tl[toff + j][lane] = lev;
        ql[j] = frcp(lev);
    }
#pragma unroll
    for (int j = 0; j < SEAS; j++) {
        float ns = fmaf(omb, ring[j], bx[j] * ql[j]);
        if (STORE) ts[toff + j][lane] = ns;
        ring[j] = ns;
        aq[j]   = a * frcp(ns);
    }
}

/* 28-step tile scan: y read as 7 LDS.128 from this lane's series-major row,
   periods assembled with compile-time component selects. */
template<bool STORE>
__device__ __forceinline__ void scan_tile(const float* myrow,
                                          float (*tl)[33], float (*ts)[33],
                                          int lane, float a, float oma,
                                          float b, float omb,
                                          float& lev, float* ring, float* aq)
{
    const float4* r4 = reinterpret_cast<const float4*>(myrow);
    float yt[SEAS];
    float4 c0 = r4[0], c1 = r4[1];
    yt[0]=c0.x; yt[1]=c0.y; yt[2]=c0.z; yt[3]=c0.w; yt[4]=c1.x; yt[5]=c1.y; yt[6]=c1.z;
    step7<STORE>(yt, tl, ts, 0, lane, a, oma, b, omb, lev, ring, aq);
    float4 c2 = r4[2], c3 = r4[3];
    yt[0]=c1.w; yt[1]=c2.x; yt[2]=c2.y; yt[3]=c2.z; yt[4]=c2.w; yt[5]=c3.x; yt[6]=c3.y;
    step7<STORE>(yt, tl, ts, 7, lane, a, oma, b, omb, lev, ring, aq);
    float4 c4 = r4[4], c5 = r4[5];
    yt[0]=c3.z; yt[1]=c3.w; yt[2]=c4.x; yt[3]=c4.y; yt[4]=c4.z; yt[5]=c4.w; yt[6]=c5.x;
    step7<STORE>(yt, tl, ts, 14, lane, a, oma, b, omb, lev, ring, aq);
    float4 c6 = r4[6];
    yt[0]=c5.y; yt[1]=c5.z; yt[2]=c5.w; yt[3]=c6.x; yt[4]=c6.y; yt[5]=c6.z; yt[6]=c6.w;
    step7<STORE>(yt, tl, ts, 21, lane, a, oma, b, omb, lev, ring, aq);
}

/* exact init + stub steps t=1..7 (scalar gmem reads; once per exact block).
   When STORE: writes L[0..7] and S[0..14] for this series. */
template<bool STORE>
__device__ __forceinline__ void stub_scan(const float* yrow, float* Lrow,
                                          float* Srow, const float* is,
                                          float a, float oma, float b, float omb,
                                          float& lev, float* ring, float* aq)
{
    float yt[SEAS];
#pragma unroll
    for (int t = 0; t < SEAS; t++) yt[t] = __ldg(yrow + 1 + t);
    lev = __fdividef(__ldg(yrow), is[0]);
    ring[0]=is[1]; ring[1]=is[2]; ring[2]=is[3]; ring[3]=is[4];
    ring[4]=is[5]; ring[5]=is[6]; ring[6]=is[0];
#pragma unroll
    for (int j = 0; j < SEAS; j++) aq[j] = a * frcp(ring[j]);
    if (STORE) {
        Lrow[0] = lev;
#pragma unroll
        for (int k = 0; k < SEAS; k++) Srow[k] = is[k];
        Srow[SEAS] = is[0];
    }
#pragma unroll
    for (int j = 0; j < SEAS; j++) {
        lev = fmaf(oma, lev, yt[j] * aq[j]);
        if (STORE) Lrow[1 + j] = lev;
        float ns = fmaf(omb, ring[j], (b * yt[j]) * frcp(lev));
        if (STORE) Srow[8 + j] = ns;
        ring[j] = ns;
        aq[j]   = a * frcp(ns);
    }
}

/* dummy kernels: keep the ncu capture (launch index 3) on passA */
__global__ void dummy_kernel() {}

/* ---- Pass A: warmup + body per relay chunk, record fine states ---- */
__global__ void __launch_bounds__(32, 21)
passA_kernel(const float* __restrict__ y, const int* __restrict__ idxs,
             const float* __restrict__ emb)
{
    __shared__ __align__(16) float ty[2][32][TS];
    const int c    = blockIdx.x / 64;
    const int sg   = blockIdx.x % 64;
    const int lane = threadIdx.x;
    const int s    = sg * 32 + lane;

    /* chunk k<=4: exact from t=1 (stub), tiles from t=8, body = last 3 tiles.
       k>=5: guess at t0 = 8+84k-364 (>=56; == 1 mod 7; == 0 mod 4).
       k=48: short body (2 fines). */
    int t0, ntiles, wtiles;
    if (c <= 4)       { t0 = 8;            ntiles = 3 * c + 3; wtiles = 3 * c; }
    else if (c == 48) { t0 = 84 * c - 356; ntiles = 15;        wtiles = 13;    }
    else              { t0 = 84 * c - 356; ntiles = 16;        wtiles = 13;    }

    const float* ygrp = y + (size_t)(sg * 32) * N_TIME;
    const uint32_t tyb0 = s2u(&ty[0][0][0]);
    const uint32_t tyb1 = s2u(&ty[1][0][0]);

    tile_cp(tyb0, ygrp, t0, lane);
    CP_COMMIT();

    float a, oma, b, omb, is[SEAS];
    load_params(idxs, emb, s, a, oma, b, omb, is);

    float lev, ring[SEAS], aq[SEAS];
    if (c <= 4) {
        stub_scan<false>(y + (size_t)s * N_TIME, 0, 0, is,
                         a, oma, b, omb, lev, ring, aq);
    } else {
        lev = __fdividef(__ldg(y + (size_t)s * N_TIME + (t0 - 1)), is[0]);
        ring[0]=is[1]; ring[1]=is[2]; ring[2]=is[3]; ring[3]=is[4];
        ring[4]=is[5]; ring[5]=is[6]; ring[6]=is[0];
#pragma unroll
        for (int j = 0; j < SEAS; j++) aq[j] = a * frcp(ring[j]);
    }

#pragma unroll 1
    for (int tile = 0; tile < ntiles; tile++) {
        const int buf = tile & 1;
        if (tile + 1 < ntiles) {
            tile_cp(buf ? tyb0 : tyb1, ygrp, t0 + (tile + 1) * TS, lane);
            CP_COMMIT();
            CP_WAIT1();
        } else {
            CP_WAIT0();
        }
        __syncwarp();

        if (tile >= wtiles) {
            const int m = 3 * c + (tile - wtiles);
            g_flev[m][s] = lev;
#pragma unroll
            for (int j = 0; j < SEAS; j++) g_fring[m][j][s] = ring[j];
        }

        scan_tile<false>(&ty[buf][lane][0], 0, 0, lane,
                         a, oma, b, omb, lev, ring, aq);
        __syncwarp();
    }
    g_endlev[c][s] = lev;
}

/* ---- Pass C: gauge chain inline, 146 fine chunks x 28 steps, stores ---- */
__global__ void __launch_bounds__(32, 24)
passC_kernel(const float* __restrict__ y, const int* __restrict__ idxs,
             const float* __restrict__ emb,
             float* __restrict__ L, float* __restrict__ S)
{
    __shared__ __align__(16) float ty[32][TS];
    __shared__ float tl[TS][33];
    __shared__ float tsb[TS][33];
    const int m    = blockIdx.x / 64;
    const int sg   = blockIdx.x % 64;
    const int lane = threadIdx.x;
    const int s    = sg * 32 + lane;

    const int tstart = 8 + TS * m;
    const float* ygrp = y + (size_t)(sg * 32) * N_TIME;

    tile_cp(s2u(&ty[0][0]), ygrp, tstart, lane);
    CP_COMMIT();

    float a, oma, b, omb, is[SEAS];
    load_params(idxs, emb, s, a, oma, b, omb, is);

    /* gauge: product over guess-started links (chunks 5..c), c = m/3 */
    const int c = m / 3;
    float gam = 1.0f;
    for (int k = 5; k <= c; k++)
        gam *= __fdividef(g_flev[3 * k][s], g_endlev[k - 1][s]);

    float lev = g_flev[m][s] * frcp(gam);
    float ring[SEAS], aq[SEAS];
#pragma unroll
    for (int j = 0; j < SEAS; j++) {
        ring[j] = g_fring[m][j][s] * gam;
        aq[j]   = a * frcp(ring[j]);
    }

    if (m == 0) {   /* stub outputs: L[0..7], S[0..14] */
        float lev2, ring2[SEAS], aq2[SEAS];
        stub_scan<true>(y + (size_t)s * N_TIME, L + (size_t)s * N_TIME,
                        S + (size_t)s * S_LEN, is,
                        a, oma, b, omb, lev2, ring2, aq2);
    }

    CP_WAIT0();
    __syncwarp();

    scan_tile<true>(&ty[lane][0], tl, tsb, lane, a, oma, b, omb, lev, ring, aq);
    __syncwarp();

    /* coalesced flush: lane = time offset (lanes 28..31 idle) */
    if (lane < TS) {
        float* Lb = L + (size_t)(sg * 32) * N_TIME + tstart + lane;
        float* Sb = S + (size_t)(sg * 32) * S_LEN + tstart + SEAS + lane;
#pragma unroll
        for (int r = 0; r < 32; r++) {
            Lb[(size_t)r * N_TIME] = tl[lane][r];
            Sb[(size_t)r * S_LEN]  = tsb[lane][r];
        }
    }
}

__global__ void windows_kernel(const float* __restrict__ y,
                               const float* __restrict__ L,
                               const float* __restrict__ S,
                               float* __restrict__ yhat,
                               float* __restrict__ ywin)
{
    const int NH = OUTPUT_SIZE * N_SERIES * INPUT_SIZE;   /* 401408 */
    const int NZ = OUTPUT_SIZE * N_SERIES * OUTPUT_SIZE;  /* 100352 */
    int i = blockIdx.x * blockDim.x + threadIdx.x;
    if (i < NH) {
        int ii   = i % INPUT_SIZE;
        int rest = i / INPUT_SIZE;
        int s    = rest % N_SERIES;
        int w    = rest / N_SERIES;
        int start = N_TIME - INPUT_SIZE - OUTPUT_SIZE + 1 + w;
        int t = start + ii;
        float lev = L[(size_t)s * N_TIME + (start + INPUT_SIZE - 1)];
        float se  = S[(size_t)s * S_LEN  + t];
        float yy  = y[(size_t)s * N_TIME + t];
        yhat[i] = logf(yy / (lev * se));
    } else if (i < NH + NZ) {
        ywin[i - NH] = 0.0f;
    }
}

extern "C" void kernel_launch(void* const* d_in, const int* in_sizes, int n_in,
                              void* d_out, int out_size) {
    const float* y    = (const float*)d_in[0];
    const int*   idxs = (const int*)  d_in[1];
    const float* emb  = (const float*)d_in[2];

    float* out  = (float*)d_out;
    float* yhat = out + OFF_YHAT;
    float* ywin = out + OFF_YWIN;
    float* L    = out + OFF_LEV;
    float* S    = out + OFF_SEAS;

    /* launches 0-2: dummies so the ncu capture (launch #3) profiles passA */
    dummy_kernel<<<1, 32>>>();
    dummy_kernel<<<1, 32>>>();
    dummy_kernel<<<1, 32>>>();

    passA_kernel<<<NCH1 * 64, 32>>>(y, idxs, emb);
    passC_kernel<<<NCH2 * 64, 32>>>(y, idxs, emb, L, S);

    const int tot = OUTPUT_SIZE * N_SERIES * (INPUT_SIZE + OUTPUT_SIZE); /* 501760 */
    windows_kernel<<<(tot + 255) / 256, 256>>>(y, L, S, yhat, ywin);
}